// round 3
// baseline (speedup 1.0000x reference)
#include <cuda_runtime.h>
#include <math.h>

// Problem constants
#define Bb   8
#define Cc   16
#define Ff   256
#define F2v  129
#define Tt   512
#define BT   4096      // Bb*Tt
#define CINv 32        // 2*Cc
#define Hh   16

// ---------------- scratch (device globals; allocation-free) ----------------
__device__ float g_xr[Bb*Cc*F2v*Tt];     // rfft real   (B,C,F2,T)
__device__ float g_xi[Bb*Cc*F2v*Tt];     // rfft imag
__device__ float g_zt[BT*F2v*CINv];      // normalized, transposed (BT,F2,32)
__device__ float g_ycat[BT*F2v*CINv];    // LSTM fwd|bwd concat    (BT,F2,32)
__device__ float g_z2r[Bb*Cc*F2v*Tt];    // linear out, real half  (B,C,F2,T)
__device__ float g_z2i[Bb*Cc*F2v*Tt];    // linear out, imag half
__device__ float g_psum[Bb*32*Tt];
__device__ float g_psq [Bb*32*Tt];
__device__ float g_mean[Bb*Tt];
__device__ float g_istd[Bb*Tt];

// ---------------- helpers ----------------
__device__ __forceinline__ float fsig(float x) {
    return __fdividef(1.0f, 1.0f + __expf(-x));
}
__device__ __forceinline__ float ftanh(float x) {
    float e = __expf(-2.0f * fabsf(x));
    float r = __fdividef(1.0f - e, 1.0f + e);
    return copysignf(r, x);
}

// ---------------- K1: rfft (naive table DFT, tiled over t) ----------------
// grid (128, 16), block 256.  block = (b*C + c, t-tile of 32)
__global__ __launch_bounds__(256) void k_rfft(const float* __restrict__ x) {
    __shared__ float tile[256 * 36];           // [f][t] pad 36
    __shared__ float ct[256], st[256];
    int bc = blockIdx.x;
    int t0 = blockIdx.y * 32;
    const float* xp = x + ((size_t)bc * Ff) * Tt + t0;

    for (int i = threadIdx.x; i < 256 * 32; i += 256) {
        int f = i >> 5, tt = i & 31;
        tile[f * 36 + tt] = xp[f * Tt + tt];
    }
    {
        float s, c;
        sincospif((float)threadIdx.x * (1.0f / 128.0f), &s, &c);
        ct[threadIdx.x] = c; st[threadIdx.x] = s;
    }
    __syncthreads();

    for (int o = threadIdx.x; o < F2v * 8; o += 256) {
        int k = o >> 3;
        int g = (o & 7) * 4;
        float ar0 = 0, ar1 = 0, ar2 = 0, ar3 = 0;
        float ai0 = 0, ai1 = 0, ai2 = 0, ai3 = 0;
        int idx = 0;
        #pragma unroll 4
        for (int f = 0; f < 256; f++) {
            float4 v = *(const float4*)&tile[f * 36 + g];
            float c = ct[idx], s = st[idx];
            ar0 = fmaf(v.x, c, ar0); ai0 = fmaf(v.x, s, ai0);
            ar1 = fmaf(v.y, c, ar1); ai1 = fmaf(v.y, s, ai1);
            ar2 = fmaf(v.z, c, ar2); ai2 = fmaf(v.z, s, ai2);
            ar3 = fmaf(v.w, c, ar3); ai3 = fmaf(v.w, s, ai3);
            idx = (idx + k) & 255;
        }
        int base = (bc * F2v + k) * Tt + t0 + g;
        float4 r  = make_float4(ar0, ar1, ar2, ar3);
        float4 im = make_float4(-ai0, -ai1, -ai2, -ai3);   // e^{-i...}
        *(float4*)&g_xr[base] = r;
        *(float4*)&g_xi[base] = im;
    }
}

// ---------------- K2a: per-(b,c2) partial sums over k ----------------
// grid (8, 32), block 512 (thread = t)
__global__ void k_stat1() {
    int b = blockIdx.x, c2 = blockIdx.y, t = threadIdx.x;
    const float* src = (c2 < 16 ? g_xr : g_xi)
                       + ((size_t)(b * Cc + (c2 & 15)) * F2v) * Tt + t;
    float s = 0.0f, s2 = 0.0f;
    for (int k = 0; k < F2v; k++) {
        float v = src[k * Tt];
        s += v;
        s2 = fmaf(v, v, s2);
    }
    g_psum[(b * 32 + c2) * Tt + t] = s;
    g_psq [(b * 32 + c2) * Tt + t] = s2;
}

// ---------------- K2a2: finalize mean / istd (ddof=1) ----------------
// grid 8, block 512
__global__ void k_stat2() {
    int b = blockIdx.x, t = threadIdx.x;
    float s = 0.0f, s2 = 0.0f;
    for (int c2 = 0; c2 < 32; c2++) {
        s  += g_psum[(b * 32 + c2) * Tt + t];
        s2 += g_psq [(b * 32 + c2) * Tt + t];
    }
    const float n = 4128.0f;            // 32 * 129
    float mean = s / n;
    float var = (s2 - s * s / n) * (1.0f / 4127.0f);
    var = fmaxf(var, 0.0f);
    g_mean[b * Tt + t] = mean;
    g_istd[b * Tt + t] = __fdividef(1.0f, sqrtf(var) + 1e-8f);
}

// ---------------- K2b: normalize + transpose to (BT, F2, 32) ----------------
// grid (8*129, 16), block 256
__global__ __launch_bounds__(256) void k_normT(const float* __restrict__ nw,
                                               const float* __restrict__ nb) {
    __shared__ float sm[32 * 33];
    int bk = blockIdx.x;
    int b = bk / F2v, k = bk - b * F2v;
    int t0 = blockIdx.y * 32;

    for (int i = threadIdx.x; i < 1024; i += 256) {
        int c2 = i >> 5, tt = i & 31;
        float v = (c2 < 16 ? g_xr : g_xi)
                  [((size_t)(b * Cc + (c2 & 15)) * F2v + k) * Tt + t0 + tt];
        v = (v - g_mean[b * Tt + t0 + tt]) * g_istd[b * Tt + t0 + tt];
        v = fmaf(v, nw[c2 * F2v + k], nb[c2 * F2v + k]);
        sm[c2 * 33 + tt] = v;
    }
    __syncthreads();
    for (int i = threadIdx.x; i < 1024; i += 256) {
        int t = i >> 5, c2 = i & 31;
        g_zt[((size_t)(b * Tt + t0 + t) * F2v + k) * CINv + c2] = sm[c2 * 33 + t];
    }
}

// ---------------- K3: bidirectional LSTM, one warp per (seq, dir) ----------------
// grid 2048, block 128 (4 warps). gw = global warp id; seq = gw>>1; dir = gw&1.
// Lane l owns gate rows l (i/f) and l+32 (g/o); h,c live in lanes 0..15.
__global__ __launch_bounds__(128, 4) void k_lstm(
    const float* __restrict__ wihf, const float* __restrict__ whhf,
    const float* __restrict__ bihf, const float* __restrict__ bhhf,
    const float* __restrict__ wihb, const float* __restrict__ whhb,
    const float* __restrict__ bihb, const float* __restrict__ bhhb) {

    int gw  = blockIdx.x * 4 + (threadIdx.x >> 5);
    int l   = threadIdx.x & 31;
    int seq = gw >> 1;
    int dir = gw & 1;

    const float* wih = dir ? wihb : wihf;
    const float* whh = dir ? whhb : whhf;
    const float* bih = dir ? bihb : bihf;
    const float* bhh = dir ? bhhb : bhhf;

    float wi0[32], wi1[32], wh0[16], wh1[16];
    #pragma unroll
    for (int j = 0; j < 32; j++) {
        wi0[j] = wih[l * 32 + j];
        wi1[j] = wih[(l + 32) * 32 + j];
    }
    #pragma unroll
    for (int j = 0; j < 16; j++) {
        wh0[j] = whh[l * 16 + j];
        wh1[j] = whh[(l + 32) * 16 + j];
    }
    float b0 = bih[l] + bhh[l];
    float b1 = bih[l + 32] + bhh[l + 32];

    float h = 0.0f, cst = 0.0f;
    int lo = l & 15;
    const unsigned FULL = 0xffffffffu;

    for (int s = 0; s < F2v; s++) {
        int f = dir ? (F2v - 1 - s) : s;
        int base = (seq * F2v + f) * CINv;
        float xv = g_zt[base + l];                      // coalesced 128B
        float a0 = b0, a1 = b1;
        #pragma unroll
        for (int j = 0; j < 32; j++) {
            float v = __shfl_sync(FULL, xv, j);
            a0 = fmaf(wi0[j], v, a0);
            a1 = fmaf(wi1[j], v, a1);
        }
        #pragma unroll
        for (int j = 0; j < 16; j++) {
            float v = __shfl_sync(FULL, h, j);
            a0 = fmaf(wh0[j], v, a0);
            a1 = fmaf(wh1[j], v, a1);
        }
        // gate redistribution: lane lo holds i(a0),g(a1); lane lo+16 holds f(a0),o(a1)
        float ia = __shfl_sync(FULL, a0, lo);
        float ga = __shfl_sync(FULL, a1, lo);
        float fa = __shfl_sync(FULL, a0, lo + 16);
        float oa = __shfl_sync(FULL, a1, lo + 16);
        cst = fmaf(fsig(fa), cst, fsig(ia) * ftanh(ga));
        h   = fsig(oa) * ftanh(cst);
        if (l < 16) g_ycat[base + dir * 16 + l] = h;
    }
}

// ---------------- K4: linear (2H->2C) + transpose back to (B,2C,F2,T) ---------
// grid (8*129, 16), block 256
__global__ __launch_bounds__(256) void k_lin(const float* __restrict__ lw,
                                             const float* __restrict__ lb) {
    __shared__ float slw[1024];
    __shared__ float slb[32];
    __shared__ float yt[32 * 33];
    int bk = blockIdx.x;
    int b = bk / F2v, k = bk - b * F2v;
    int t0 = blockIdx.y * 32;

    for (int i = threadIdx.x; i < 1024; i += 256) slw[i] = lw[i];
    if (threadIdx.x < 32) slb[threadIdx.x] = lb[threadIdx.x];
    for (int i = threadIdx.x; i < 1024; i += 256) {
        int t = i >> 5, j = i & 31;
        yt[t * 33 + j] = g_ycat[((size_t)(b * Tt + t0 + t) * F2v + k) * CINv + j];
    }
    __syncthreads();

    for (int i = threadIdx.x; i < 1024; i += 256) {
        int c2 = i >> 5, t = i & 31;
        float acc = slb[c2];
        #pragma unroll
        for (int j = 0; j < 32; j++)
            acc = fmaf(slw[c2 * 32 + j], yt[t * 33 + j], acc);
        if (c2 < 16)
            g_z2r[((size_t)(b * Cc + c2) * F2v + k) * Tt + t0 + t] = acc;
        else
            g_z2i[((size_t)(b * Cc + c2 - 16) * F2v + k) * Tt + t0 + t] = acc;
    }
}

// ---------------- K5: complex multiply + irfft(256) ----------------
// grid (128, 16), block 256
__global__ __launch_bounds__(256) void k_irfft(float* __restrict__ out) {
    __shared__ float prt[F2v * 36];
    __shared__ float pit[F2v * 36];
    __shared__ float ct[256], st[256];
    int bc = blockIdx.x;
    int t0 = blockIdx.y * 32;

    for (int i = threadIdx.x; i < F2v * 32; i += 256) {
        int k = i >> 5, tt = i & 31;
        int g = (bc * F2v + k) * Tt + t0 + tt;
        float ar = g_z2r[g], ai = g_z2i[g];
        float xr = g_xr[g],  xi = g_xi[g];
        prt[k * 36 + tt] = ar * xr - ai * xi;
        pit[k * 36 + tt] = fmaf(ar, xi, ai * xr);
    }
    {
        float s, c;
        sincospif((float)threadIdx.x * (1.0f / 128.0f), &s, &c);
        ct[threadIdx.x] = c; st[threadIdx.x] = s;
    }
    __syncthreads();

    for (int o = threadIdx.x; o < 256 * 8; o += 256) {
        int n  = o >> 3;
        int g4 = (o & 7) * 4;
        float sgn = (n & 1) ? -1.0f : 1.0f;
        float4 p0 = *(const float4*)&prt[0   * 36 + g4];
        float4 pN = *(const float4*)&prt[128 * 36 + g4];
        float a0 = 0.5f * fmaf(sgn, pN.x, p0.x);
        float a1 = 0.5f * fmaf(sgn, pN.y, p0.y);
        float a2 = 0.5f * fmaf(sgn, pN.z, p0.z);
        float a3 = 0.5f * fmaf(sgn, pN.w, p0.w);
        int idx = n;
        #pragma unroll 4
        for (int k = 1; k < 128; k++) {
            float c = ct[idx];
            float ns = -st[idx];
            float4 pr = *(const float4*)&prt[k * 36 + g4];
            float4 pi = *(const float4*)&pit[k * 36 + g4];
            a0 = fmaf(pr.x, c, a0); a0 = fmaf(pi.x, ns, a0);
            a1 = fmaf(pr.y, c, a1); a1 = fmaf(pi.y, ns, a1);
            a2 = fmaf(pr.z, c, a2); a2 = fmaf(pi.z, ns, a2);
            a3 = fmaf(pr.w, c, a3); a3 = fmaf(pi.w, ns, a3);
            idx = (idx + n) & 255;
        }
        const float inv = 1.0f / 128.0f;   // (1/256) * 2 folded
        int base = (bc * Ff + n) * Tt + t0 + g4;
        float4 r = make_float4(a0 * inv, a1 * inv, a2 * inv, a3 * inv);
        *(float4*)&out[base] = r;
    }
}

// ---------------- launch ----------------
extern "C" void kernel_launch(void* const* d_in, const int* in_sizes, int n_in,
                              void* d_out, int out_size) {
    const float* x      = (const float*)d_in[0];
    const float* norm_w = (const float*)d_in[1];
    const float* norm_b = (const float*)d_in[2];
    const float* w_ih_f = (const float*)d_in[3];
    const float* w_hh_f = (const float*)d_in[4];
    const float* b_ih_f = (const float*)d_in[5];
    const float* b_hh_f = (const float*)d_in[6];
    const float* w_ih_b = (const float*)d_in[7];
    const float* w_hh_b = (const float*)d_in[8];
    const float* b_ih_b = (const float*)d_in[9];
    const float* b_hh_b = (const float*)d_in[10];
    const float* lin_w  = (const float*)d_in[11];
    const float* lin_b  = (const float*)d_in[12];
    float* out = (float*)d_out;

    k_rfft <<<dim3(Bb * Cc, Tt / 32), 256>>>(x);
    k_stat1<<<dim3(Bb, 32), Tt>>>();
    k_stat2<<<Bb, Tt>>>();
    k_normT<<<dim3(Bb * F2v, Tt / 32), 256>>>(norm_w, norm_b);
    k_lstm <<<2048, 128>>>(w_ih_f, w_hh_f, b_ih_f, b_hh_f,
                           w_ih_b, w_hh_b, b_ih_b, b_hh_b);
    k_lin  <<<dim3(Bb * F2v, Tt / 32), 256>>>(lin_w, lin_b);
    k_irfft<<<dim3(Bb * Cc, Tt / 32), 256>>>(out);
}

// round 4
// speedup vs baseline: 1.0012x; 1.0012x over previous
#include <cuda_runtime.h>
#include <math.h>

// Problem constants
#define Bb   8
#define Cc   16
#define Ff   256
#define F2v  129
#define Tt   512
#define BT   4096      // Bb*Tt
#define CINv 32        // 2*Cc
#define Hh   16

// ---------------- scratch (device globals; allocation-free) ----------------
__device__ float g_xr[Bb*Cc*F2v*Tt];     // rfft real   (B,C,F2,T)
__device__ float g_xi[Bb*Cc*F2v*Tt];     // rfft imag
__device__ float g_zt[BT*F2v*CINv];      // normalized, transposed (BT,F2,32)
__device__ float g_ycat[BT*F2v*CINv];    // LSTM fwd|bwd concat    (BT,F2,32)
__device__ float g_z2r[Bb*Cc*F2v*Tt];    // linear out, real half  (B,C,F2,T)
__device__ float g_z2i[Bb*Cc*F2v*Tt];    // linear out, imag half
__device__ float g_psum[Bb*32*Tt];
__device__ float g_psq [Bb*32*Tt];
__device__ float g_mean[Bb*Tt];
__device__ float g_istd[Bb*Tt];

// ---------------- helpers ----------------
__device__ __forceinline__ float fsig(float x) {
    return __fdividef(1.0f, 1.0f + __expf(-x));
}
__device__ __forceinline__ float ftanh(float x) {
    float e = __expf(-2.0f * fabsf(x));
    float r = __fdividef(1.0f - e, 1.0f + e);
    return copysignf(r, x);
}

// ---------------- K1: rfft (naive table DFT, tiled over t) ----------------
// grid (128, 16), block 256.  block = (b*C + c, t-tile of 32)
__global__ __launch_bounds__(256) void k_rfft(const float* __restrict__ x) {
    __shared__ float tile[256 * 36];           // [f][t] pad 36
    __shared__ float ct[256], st[256];
    int bc = blockIdx.x;
    int t0 = blockIdx.y * 32;
    const float* xp = x + ((size_t)bc * Ff) * Tt + t0;

    for (int i = threadIdx.x; i < 256 * 32; i += 256) {
        int f = i >> 5, tt = i & 31;
        tile[f * 36 + tt] = xp[f * Tt + tt];
    }
    {
        float s, c;
        sincospif((float)threadIdx.x * (1.0f / 128.0f), &s, &c);
        ct[threadIdx.x] = c; st[threadIdx.x] = s;
    }
    __syncthreads();

    for (int o = threadIdx.x; o < F2v * 8; o += 256) {
        int k = o >> 3;
        int g = (o & 7) * 4;
        float ar0 = 0, ar1 = 0, ar2 = 0, ar3 = 0;
        float ai0 = 0, ai1 = 0, ai2 = 0, ai3 = 0;
        int idx = 0;
        #pragma unroll 4
        for (int f = 0; f < 256; f++) {
            float4 v = *(const float4*)&tile[f * 36 + g];
            float c = ct[idx], s = st[idx];
            ar0 = fmaf(v.x, c, ar0); ai0 = fmaf(v.x, s, ai0);
            ar1 = fmaf(v.y, c, ar1); ai1 = fmaf(v.y, s, ai1);
            ar2 = fmaf(v.z, c, ar2); ai2 = fmaf(v.z, s, ai2);
            ar3 = fmaf(v.w, c, ar3); ai3 = fmaf(v.w, s, ai3);
            idx = (idx + k) & 255;
        }
        int base = (bc * F2v + k) * Tt + t0 + g;
        float4 r  = make_float4(ar0, ar1, ar2, ar3);
        float4 im = make_float4(-ai0, -ai1, -ai2, -ai3);   // e^{-i...}
        *(float4*)&g_xr[base] = r;
        *(float4*)&g_xi[base] = im;
    }
}

// ---------------- K2a: per-(b,c2) partial sums over k ----------------
// grid (8, 32), block 512 (thread = t)
__global__ void k_stat1() {
    int b = blockIdx.x, c2 = blockIdx.y, t = threadIdx.x;
    const float* src = (c2 < 16 ? g_xr : g_xi)
                       + ((size_t)(b * Cc + (c2 & 15)) * F2v) * Tt + t;
    float s = 0.0f, s2 = 0.0f;
    for (int k = 0; k < F2v; k++) {
        float v = src[k * Tt];
        s += v;
        s2 = fmaf(v, v, s2);
    }
    g_psum[(b * 32 + c2) * Tt + t] = s;
    g_psq [(b * 32 + c2) * Tt + t] = s2;
}

// ---------------- K2a2: finalize mean / istd (ddof=1) ----------------
// grid 8, block 512
__global__ void k_stat2() {
    int b = blockIdx.x, t = threadIdx.x;
    float s = 0.0f, s2 = 0.0f;
    for (int c2 = 0; c2 < 32; c2++) {
        s  += g_psum[(b * 32 + c2) * Tt + t];
        s2 += g_psq [(b * 32 + c2) * Tt + t];
    }
    const float n = 4128.0f;            // 32 * 129
    float mean = s / n;
    float var = (s2 - s * s / n) * (1.0f / 4127.0f);
    var = fmaxf(var, 0.0f);
    g_mean[b * Tt + t] = mean;
    g_istd[b * Tt + t] = __fdividef(1.0f, sqrtf(var) + 1e-8f);
}

// ---------------- K2b: normalize + transpose to (BT, F2, 32) ----------------
// grid (8*129, 16), block 256
__global__ __launch_bounds__(256) void k_normT(const float* __restrict__ nw,
                                               const float* __restrict__ nb) {
    __shared__ float sm[32 * 33];
    int bk = blockIdx.x;
    int b = bk / F2v, k = bk - b * F2v;
    int t0 = blockIdx.y * 32;

    for (int i = threadIdx.x; i < 1024; i += 256) {
        int c2 = i >> 5, tt = i & 31;
        float v = (c2 < 16 ? g_xr : g_xi)
                  [((size_t)(b * Cc + (c2 & 15)) * F2v + k) * Tt + t0 + tt];
        v = (v - g_mean[b * Tt + t0 + tt]) * g_istd[b * Tt + t0 + tt];
        v = fmaf(v, nw[c2 * F2v + k], nb[c2 * F2v + k]);
        sm[c2 * 33 + tt] = v;
    }
    __syncthreads();
    for (int i = threadIdx.x; i < 1024; i += 256) {
        int t = i >> 5, c2 = i & 31;
        g_zt[((size_t)(b * Tt + t0 + t) * F2v + k) * CINv + c2] = sm[c2 * 33 + t];
    }
}

// ---------------- K3: bidirectional LSTM, one warp per (seq, dir) ----------------
// grid 2048, block 128 (4 warps). gw = global warp id; seq = gw>>1; dir = gw&1.
// Lane l owns gate rows l (i/f) and l+32 (g/o); h,c live in lanes 0..15.
__global__ __launch_bounds__(128, 4) void k_lstm(
    const float* __restrict__ wihf, const float* __restrict__ whhf,
    const float* __restrict__ bihf, const float* __restrict__ bhhf,
    const float* __restrict__ wihb, const float* __restrict__ whhb,
    const float* __restrict__ bihb, const float* __restrict__ bhhb) {

    int gw  = blockIdx.x * 4 + (threadIdx.x >> 5);
    int l   = threadIdx.x & 31;
    int seq = gw >> 1;
    int dir = gw & 1;

    const float* wih = dir ? wihb : wihf;
    const float* whh = dir ? whhb : whhf;
    const float* bih = dir ? bihb : bihf;
    const float* bhh = dir ? bhhb : bhhf;

    float wi0[32], wi1[32], wh0[16], wh1[16];
    #pragma unroll
    for (int j = 0; j < 32; j++) {
        wi0[j] = wih[l * 32 + j];
        wi1[j] = wih[(l + 32) * 32 + j];
    }
    #pragma unroll
    for (int j = 0; j < 16; j++) {
        wh0[j] = whh[l * 16 + j];
        wh1[j] = whh[(l + 32) * 16 + j];
    }
    float b0 = bih[l] + bhh[l];
    float b1 = bih[l + 32] + bhh[l + 32];

    float h = 0.0f, cst = 0.0f;
    int lo = l & 15;
    const unsigned FULL = 0xffffffffu;

    for (int s = 0; s < F2v; s++) {
        int f = dir ? (F2v - 1 - s) : s;
        int base = (seq * F2v + f) * CINv;
        float xv = g_zt[base + l];                      // coalesced 128B
        float a0 = b0, a1 = b1;
        #pragma unroll
        for (int j = 0; j < 32; j++) {
            float v = __shfl_sync(FULL, xv, j);
            a0 = fmaf(wi0[j], v, a0);
            a1 = fmaf(wi1[j], v, a1);
        }
        #pragma unroll
        for (int j = 0; j < 16; j++) {
            float v = __shfl_sync(FULL, h, j);
            a0 = fmaf(wh0[j], v, a0);
            a1 = fmaf(wh1[j], v, a1);
        }
        // gate redistribution: lane lo holds i(a0),g(a1); lane lo+16 holds f(a0),o(a1)
        float ia = __shfl_sync(FULL, a0, lo);
        float ga = __shfl_sync(FULL, a1, lo);
        float fa = __shfl_sync(FULL, a0, lo + 16);
        float oa = __shfl_sync(FULL, a1, lo + 16);
        cst = fmaf(fsig(fa), cst, fsig(ia) * ftanh(ga));
        h   = fsig(oa) * ftanh(cst);
        if (l < 16) g_ycat[base + dir * 16 + l] = h;
    }
}

// ---------------- K4: linear (2H->2C) + transpose back to (B,2C,F2,T) ---------
// grid (8*129, 16), block 256
__global__ __launch_bounds__(256) void k_lin(const float* __restrict__ lw,
                                             const float* __restrict__ lb) {
    __shared__ float slw[1024];
    __shared__ float slb[32];
    __shared__ float yt[32 * 33];
    int bk = blockIdx.x;
    int b = bk / F2v, k = bk - b * F2v;
    int t0 = blockIdx.y * 32;

    for (int i = threadIdx.x; i < 1024; i += 256) slw[i] = lw[i];
    if (threadIdx.x < 32) slb[threadIdx.x] = lb[threadIdx.x];
    for (int i = threadIdx.x; i < 1024; i += 256) {
        int t = i >> 5, j = i & 31;
        yt[t * 33 + j] = g_ycat[((size_t)(b * Tt + t0 + t) * F2v + k) * CINv + j];
    }
    __syncthreads();

    for (int i = threadIdx.x; i < 1024; i += 256) {
        int c2 = i >> 5, t = i & 31;
        float acc = slb[c2];
        #pragma unroll
        for (int j = 0; j < 32; j++)
            acc = fmaf(slw[c2 * 32 + j], yt[t * 33 + j], acc);
        if (c2 < 16)
            g_z2r[((size_t)(b * Cc + c2) * F2v + k) * Tt + t0 + t] = acc;
        else
            g_z2i[((size_t)(b * Cc + c2 - 16) * F2v + k) * Tt + t0 + t] = acc;
    }
}

// ---------------- K5: complex multiply + irfft(256) ----------------
// grid (128, 16), block 256
__global__ __launch_bounds__(256) void k_irfft(float* __restrict__ out) {
    __shared__ float prt[F2v * 36];
    __shared__ float pit[F2v * 36];
    __shared__ float ct[256], st[256];
    int bc = blockIdx.x;
    int t0 = blockIdx.y * 32;

    for (int i = threadIdx.x; i < F2v * 32; i += 256) {
        int k = i >> 5, tt = i & 31;
        int g = (bc * F2v + k) * Tt + t0 + tt;
        float ar = g_z2r[g], ai = g_z2i[g];
        float xr = g_xr[g],  xi = g_xi[g];
        prt[k * 36 + tt] = ar * xr - ai * xi;
        pit[k * 36 + tt] = fmaf(ar, xi, ai * xr);
    }
    {
        float s, c;
        sincospif((float)threadIdx.x * (1.0f / 128.0f), &s, &c);
        ct[threadIdx.x] = c; st[threadIdx.x] = s;
    }
    __syncthreads();

    for (int o = threadIdx.x; o < 256 * 8; o += 256) {
        int n  = o >> 3;
        int g4 = (o & 7) * 4;
        float sgn = (n & 1) ? -1.0f : 1.0f;
        float4 p0 = *(const float4*)&prt[0   * 36 + g4];
        float4 pN = *(const float4*)&prt[128 * 36 + g4];
        float a0 = 0.5f * fmaf(sgn, pN.x, p0.x);
        float a1 = 0.5f * fmaf(sgn, pN.y, p0.y);
        float a2 = 0.5f * fmaf(sgn, pN.z, p0.z);
        float a3 = 0.5f * fmaf(sgn, pN.w, p0.w);
        int idx = n;
        #pragma unroll 4
        for (int k = 1; k < 128; k++) {
            float c = ct[idx];
            float ns = -st[idx];
            float4 pr = *(const float4*)&prt[k * 36 + g4];
            float4 pi = *(const float4*)&pit[k * 36 + g4];
            a0 = fmaf(pr.x, c, a0); a0 = fmaf(pi.x, ns, a0);
            a1 = fmaf(pr.y, c, a1); a1 = fmaf(pi.y, ns, a1);
            a2 = fmaf(pr.z, c, a2); a2 = fmaf(pi.z, ns, a2);
            a3 = fmaf(pr.w, c, a3); a3 = fmaf(pi.w, ns, a3);
            idx = (idx + n) & 255;
        }
        const float inv = 1.0f / 128.0f;   // (1/256) * 2 folded
        int base = (bc * Ff + n) * Tt + t0 + g4;
        float4 r = make_float4(a0 * inv, a1 * inv, a2 * inv, a3 * inv);
        *(float4*)&out[base] = r;
    }
}

// ---------------- launch ----------------
extern "C" void kernel_launch(void* const* d_in, const int* in_sizes, int n_in,
                              void* d_out, int out_size) {
    const float* x      = (const float*)d_in[0];
    const float* norm_w = (const float*)d_in[1];
    const float* norm_b = (const float*)d_in[2];
    const float* w_ih_f = (const float*)d_in[3];
    const float* w_hh_f = (const float*)d_in[4];
    const float* b_ih_f = (const float*)d_in[5];
    const float* b_hh_f = (const float*)d_in[6];
    const float* w_ih_b = (const float*)d_in[7];
    const float* w_hh_b = (const float*)d_in[8];
    const float* b_ih_b = (const float*)d_in[9];
    const float* b_hh_b = (const float*)d_in[10];
    const float* lin_w  = (const float*)d_in[11];
    const float* lin_b  = (const float*)d_in[12];
    float* out = (float*)d_out;

    k_rfft <<<dim3(Bb * Cc, Tt / 32), 256>>>(x);
    k_stat1<<<dim3(Bb, 32), Tt>>>();
    k_stat2<<<Bb, Tt>>>();
    k_normT<<<dim3(Bb * F2v, Tt / 32), 256>>>(norm_w, norm_b);
    k_lstm <<<2048, 128>>>(w_ih_f, w_hh_f, b_ih_f, b_hh_f,
                           w_ih_b, w_hh_b, b_ih_b, b_hh_b);
    k_lin  <<<dim3(Bb * F2v, Tt / 32), 256>>>(lin_w, lin_b);
    k_irfft<<<dim3(Bb * Cc, Tt / 32), 256>>>(out);
}

// round 5
// speedup vs baseline: 1.0026x; 1.0014x over previous
#include <cuda_runtime.h>
#include <math.h>

// Problem constants
#define Bb   8
#define Cc   16
#define Ff   256
#define F2v  129
#define Tt   512
#define BT   4096      // Bb*Tt
#define CINv 32        // 2*Cc
#define Hh   16

// ---------------- scratch (device globals; allocation-free) ----------------
__device__ float g_xr[Bb*Cc*F2v*Tt];     // rfft real   (B,C,F2,T)
__device__ float g_xi[Bb*Cc*F2v*Tt];     // rfft imag
__device__ float g_zt[BT*F2v*CINv];      // normalized, transposed (BT,F2,32)
__device__ float g_ycat[BT*F2v*CINv];    // LSTM fwd|bwd concat    (BT,F2,32)
__device__ float g_z2r[Bb*Cc*F2v*Tt];    // linear out, real half  (B,C,F2,T)
__device__ float g_z2i[Bb*Cc*F2v*Tt];    // linear out, imag half
__device__ float g_psum[Bb*32*Tt];
__device__ float g_psq [Bb*32*Tt];
__device__ float g_mean[Bb*Tt];
__device__ float g_istd[Bb*Tt];

// ---------------- helpers ----------------
__device__ __forceinline__ float fsig(float x) {
    return __fdividef(1.0f, 1.0f + __expf(-x));
}
__device__ __forceinline__ float ftanh(float x) {
    float e = __expf(-2.0f * fabsf(x));
    float r = __fdividef(1.0f - e, 1.0f + e);
    return copysignf(r, x);
}

// ---------------- K1: rfft (naive table DFT, tiled over t) ----------------
// grid (128, 16), block 256.  block = (b*C + c, t-tile of 32)
__global__ __launch_bounds__(256) void k_rfft(const float* __restrict__ x) {
    __shared__ float tile[256 * 36];           // [f][t] pad 36
    __shared__ float ct[256], st[256];
    int bc = blockIdx.x;
    int t0 = blockIdx.y * 32;
    const float* xp = x + ((size_t)bc * Ff) * Tt + t0;

    for (int i = threadIdx.x; i < 256 * 32; i += 256) {
        int f = i >> 5, tt = i & 31;
        tile[f * 36 + tt] = xp[f * Tt + tt];
    }
    {
        float s, c;
        sincospif((float)threadIdx.x * (1.0f / 128.0f), &s, &c);
        ct[threadIdx.x] = c; st[threadIdx.x] = s;
    }
    __syncthreads();

    for (int o = threadIdx.x; o < F2v * 8; o += 256) {
        int k = o >> 3;
        int g = (o & 7) * 4;
        float ar0 = 0, ar1 = 0, ar2 = 0, ar3 = 0;
        float ai0 = 0, ai1 = 0, ai2 = 0, ai3 = 0;
        int idx = 0;
        #pragma unroll 4
        for (int f = 0; f < 256; f++) {
            float4 v = *(const float4*)&tile[f * 36 + g];
            float c = ct[idx], s = st[idx];
            ar0 = fmaf(v.x, c, ar0); ai0 = fmaf(v.x, s, ai0);
            ar1 = fmaf(v.y, c, ar1); ai1 = fmaf(v.y, s, ai1);
            ar2 = fmaf(v.z, c, ar2); ai2 = fmaf(v.z, s, ai2);
            ar3 = fmaf(v.w, c, ar3); ai3 = fmaf(v.w, s, ai3);
            idx = (idx + k) & 255;
        }
        int base = (bc * F2v + k) * Tt + t0 + g;
        float4 r  = make_float4(ar0, ar1, ar2, ar3);
        float4 im = make_float4(-ai0, -ai1, -ai2, -ai3);   // e^{-i...}
        *(float4*)&g_xr[base] = r;
        *(float4*)&g_xi[base] = im;
    }
}

// ---------------- K2a: per-(b,c2) partial sums over k ----------------
// grid (8, 32), block 512 (thread = t)
__global__ void k_stat1() {
    int b = blockIdx.x, c2 = blockIdx.y, t = threadIdx.x;
    const float* src = (c2 < 16 ? g_xr : g_xi)
                       + ((size_t)(b * Cc + (c2 & 15)) * F2v) * Tt + t;
    float s = 0.0f, s2 = 0.0f;
    for (int k = 0; k < F2v; k++) {
        float v = src[k * Tt];
        s += v;
        s2 = fmaf(v, v, s2);
    }
    g_psum[(b * 32 + c2) * Tt + t] = s;
    g_psq [(b * 32 + c2) * Tt + t] = s2;
}

// ---------------- K2a2: finalize mean / istd (ddof=1) ----------------
// grid 8, block 512
__global__ void k_stat2() {
    int b = blockIdx.x, t = threadIdx.x;
    float s = 0.0f, s2 = 0.0f;
    for (int c2 = 0; c2 < 32; c2++) {
        s  += g_psum[(b * 32 + c2) * Tt + t];
        s2 += g_psq [(b * 32 + c2) * Tt + t];
    }
    const float n = 4128.0f;            // 32 * 129
    float mean = s / n;
    float var = (s2 - s * s / n) * (1.0f / 4127.0f);
    var = fmaxf(var, 0.0f);
    g_mean[b * Tt + t] = mean;
    g_istd[b * Tt + t] = __fdividef(1.0f, sqrtf(var) + 1e-8f);
}

// ---------------- K2b: normalize + transpose to (BT, F2, 32) ----------------
// grid (8*129, 16), block 256
__global__ __launch_bounds__(256) void k_normT(const float* __restrict__ nw,
                                               const float* __restrict__ nb) {
    __shared__ float sm[32 * 33];
    int bk = blockIdx.x;
    int b = bk / F2v, k = bk - b * F2v;
    int t0 = blockIdx.y * 32;

    for (int i = threadIdx.x; i < 1024; i += 256) {
        int c2 = i >> 5, tt = i & 31;
        float v = (c2 < 16 ? g_xr : g_xi)
                  [((size_t)(b * Cc + (c2 & 15)) * F2v + k) * Tt + t0 + tt];
        v = (v - g_mean[b * Tt + t0 + tt]) * g_istd[b * Tt + t0 + tt];
        v = fmaf(v, nw[c2 * F2v + k], nb[c2 * F2v + k]);
        sm[c2 * 33 + tt] = v;
    }
    __syncthreads();
    for (int i = threadIdx.x; i < 1024; i += 256) {
        int t = i >> 5, c2 = i & 31;
        g_zt[((size_t)(b * Tt + t0 + t) * F2v + k) * CINv + c2] = sm[c2 * 33 + t];
    }
}

// ---------------- K3: bidirectional LSTM, one warp per (seq, dir) ----------------
// grid 2048, block 128 (4 warps). gw = global warp id; seq = gw>>1; dir = gw&1.
// Lane l owns gate rows l (i/f) and l+32 (g/o); h,c live in lanes 0..15.
__global__ __launch_bounds__(128, 4) void k_lstm(
    const float* __restrict__ wihf, const float* __restrict__ whhf,
    const float* __restrict__ bihf, const float* __restrict__ bhhf,
    const float* __restrict__ wihb, const float* __restrict__ whhb,
    const float* __restrict__ bihb, const float* __restrict__ bhhb) {

    int gw  = blockIdx.x * 4 + (threadIdx.x >> 5);
    int l   = threadIdx.x & 31;
    int seq = gw >> 1;
    int dir = gw & 1;

    const float* wih = dir ? wihb : wihf;
    const float* whh = dir ? whhb : whhf;
    const float* bih = dir ? bihb : bihf;
    const float* bhh = dir ? bhhb : bhhf;

    float wi0[32], wi1[32], wh0[16], wh1[16];
    #pragma unroll
    for (int j = 0; j < 32; j++) {
        wi0[j] = wih[l * 32 + j];
        wi1[j] = wih[(l + 32) * 32 + j];
    }
    #pragma unroll
    for (int j = 0; j < 16; j++) {
        wh0[j] = whh[l * 16 + j];
        wh1[j] = whh[(l + 32) * 16 + j];
    }
    float b0 = bih[l] + bhh[l];
    float b1 = bih[l + 32] + bhh[l + 32];

    float h = 0.0f, cst = 0.0f;
    int lo = l & 15;
    const unsigned FULL = 0xffffffffu;

    for (int s = 0; s < F2v; s++) {
        int f = dir ? (F2v - 1 - s) : s;
        int base = (seq * F2v + f) * CINv;
        float xv = g_zt[base + l];                      // coalesced 128B
        float a0 = b0, a1 = b1;
        #pragma unroll
        for (int j = 0; j < 32; j++) {
            float v = __shfl_sync(FULL, xv, j);
            a0 = fmaf(wi0[j], v, a0);
            a1 = fmaf(wi1[j], v, a1);
        }
        #pragma unroll
        for (int j = 0; j < 16; j++) {
            float v = __shfl_sync(FULL, h, j);
            a0 = fmaf(wh0[j], v, a0);
            a1 = fmaf(wh1[j], v, a1);
        }
        // gate redistribution: lane lo holds i(a0),g(a1); lane lo+16 holds f(a0),o(a1)
        float ia = __shfl_sync(FULL, a0, lo);
        float ga = __shfl_sync(FULL, a1, lo);
        float fa = __shfl_sync(FULL, a0, lo + 16);
        float oa = __shfl_sync(FULL, a1, lo + 16);
        cst = fmaf(fsig(fa), cst, fsig(ia) * ftanh(ga));
        h   = fsig(oa) * ftanh(cst);
        if (l < 16) g_ycat[base + dir * 16 + l] = h;
    }
}

// ---------------- K4: linear (2H->2C) + transpose back to (B,2C,F2,T) ---------
// grid (8*129, 16), block 256
__global__ __launch_bounds__(256) void k_lin(const float* __restrict__ lw,
                                             const float* __restrict__ lb) {
    __shared__ float slw[1024];
    __shared__ float slb[32];
    __shared__ float yt[32 * 33];
    int bk = blockIdx.x;
    int b = bk / F2v, k = bk - b * F2v;
    int t0 = blockIdx.y * 32;

    for (int i = threadIdx.x; i < 1024; i += 256) slw[i] = lw[i];
    if (threadIdx.x < 32) slb[threadIdx.x] = lb[threadIdx.x];
    for (int i = threadIdx.x; i < 1024; i += 256) {
        int t = i >> 5, j = i & 31;
        yt[t * 33 + j] = g_ycat[((size_t)(b * Tt + t0 + t) * F2v + k) * CINv + j];
    }
    __syncthreads();

    for (int i = threadIdx.x; i < 1024; i += 256) {
        int c2 = i >> 5, t = i & 31;
        float acc = slb[c2];
        #pragma unroll
        for (int j = 0; j < 32; j++)
            acc = fmaf(slw[c2 * 32 + j], yt[t * 33 + j], acc);
        if (c2 < 16)
            g_z2r[((size_t)(b * Cc + c2) * F2v + k) * Tt + t0 + t] = acc;
        else
            g_z2i[((size_t)(b * Cc + c2 - 16) * F2v + k) * Tt + t0 + t] = acc;
    }
}

// ---------------- K5: complex multiply + irfft(256) ----------------
// grid (128, 16), block 256
__global__ __launch_bounds__(256) void k_irfft(float* __restrict__ out) {
    __shared__ float prt[F2v * 36];
    __shared__ float pit[F2v * 36];
    __shared__ float ct[256], st[256];
    int bc = blockIdx.x;
    int t0 = blockIdx.y * 32;

    for (int i = threadIdx.x; i < F2v * 32; i += 256) {
        int k = i >> 5, tt = i & 31;
        int g = (bc * F2v + k) * Tt + t0 + tt;
        float ar = g_z2r[g], ai = g_z2i[g];
        float xr = g_xr[g],  xi = g_xi[g];
        prt[k * 36 + tt] = ar * xr - ai * xi;
        pit[k * 36 + tt] = fmaf(ar, xi, ai * xr);
    }
    {
        float s, c;
        sincospif((float)threadIdx.x * (1.0f / 128.0f), &s, &c);
        ct[threadIdx.x] = c; st[threadIdx.x] = s;
    }
    __syncthreads();

    for (int o = threadIdx.x; o < 256 * 8; o += 256) {
        int n  = o >> 3;
        int g4 = (o & 7) * 4;
        float sgn = (n & 1) ? -1.0f : 1.0f;
        float4 p0 = *(const float4*)&prt[0   * 36 + g4];
        float4 pN = *(const float4*)&prt[128 * 36 + g4];
        float a0 = 0.5f * fmaf(sgn, pN.x, p0.x);
        float a1 = 0.5f * fmaf(sgn, pN.y, p0.y);
        float a2 = 0.5f * fmaf(sgn, pN.z, p0.z);
        float a3 = 0.5f * fmaf(sgn, pN.w, p0.w);
        int idx = n;
        #pragma unroll 4
        for (int k = 1; k < 128; k++) {
            float c = ct[idx];
            float ns = -st[idx];
            float4 pr = *(const float4*)&prt[k * 36 + g4];
            float4 pi = *(const float4*)&pit[k * 36 + g4];
            a0 = fmaf(pr.x, c, a0); a0 = fmaf(pi.x, ns, a0);
            a1 = fmaf(pr.y, c, a1); a1 = fmaf(pi.y, ns, a1);
            a2 = fmaf(pr.z, c, a2); a2 = fmaf(pi.z, ns, a2);
            a3 = fmaf(pr.w, c, a3); a3 = fmaf(pi.w, ns, a3);
            idx = (idx + n) & 255;
        }
        const float inv = 1.0f / 128.0f;   // (1/256) * 2 folded
        int base = (bc * Ff + n) * Tt + t0 + g4;
        float4 r = make_float4(a0 * inv, a1 * inv, a2 * inv, a3 * inv);
        *(float4*)&out[base] = r;
    }
}

// ---------------- launch ----------------
extern "C" void kernel_launch(void* const* d_in, const int* in_sizes, int n_in,
                              void* d_out, int out_size) {
    const float* x      = (const float*)d_in[0];
    const float* norm_w = (const float*)d_in[1];
    const float* norm_b = (const float*)d_in[2];
    const float* w_ih_f = (const float*)d_in[3];
    const float* w_hh_f = (const float*)d_in[4];
    const float* b_ih_f = (const float*)d_in[5];
    const float* b_hh_f = (const float*)d_in[6];
    const float* w_ih_b = (const float*)d_in[7];
    const float* w_hh_b = (const float*)d_in[8];
    const float* b_ih_b = (const float*)d_in[9];
    const float* b_hh_b = (const float*)d_in[10];
    const float* lin_w  = (const float*)d_in[11];
    const float* lin_b  = (const float*)d_in[12];
    float* out = (float*)d_out;

    k_rfft <<<dim3(Bb * Cc, Tt / 32), 256>>>(x);
    k_stat1<<<dim3(Bb, 32), Tt>>>();
    k_stat2<<<Bb, Tt>>>();
    k_normT<<<dim3(Bb * F2v, Tt / 32), 256>>>(norm_w, norm_b);
    k_lstm <<<2048, 128>>>(w_ih_f, w_hh_f, b_ih_f, b_hh_f,
                           w_ih_b, w_hh_b, b_ih_b, b_hh_b);
    k_lin  <<<dim3(Bb * F2v, Tt / 32), 256>>>(lin_w, lin_b);
    k_irfft<<<dim3(Bb * Cc, Tt / 32), 256>>>(out);
}